// round 8
// baseline (speedup 1.0000x reference)
#include <cuda_runtime.h>

// KMeans N=30000, D=64, K=500, Lloyd, early exit at assignment fixed point.
// R7: Hamerly-style bound pruning + incremental cluster sums.
//  - per-point ub/lb bounds; prune scan when ub < lb (provably same argmin)
//  - block-local queue of scan-needed points; full fast-path when queue big,
//    lane-per-centroid coalesced path (transposed centroids) when small
//  - sums maintained incrementally (+/- only on assignment change)

#define NP        30000
#define DIM       64
#define KC        500
#define KCP       512         // padded K for transposed layout
#define MAX_ITERS 1000
#define EPSV      1e-6f
#define TPB       256
#define HKC       (KC / 2)
#define QTHRESH   80
#define QCAP      208
#define SLACK_SET 1e-4f
#define DRIFT     1e-6f
#define BIGF      1e30f

typedef unsigned long long ull;

#define FMA2(d, a, b, c) \
    asm("fma.rn.f32x2 %0, %1, %2, %3;" : "=l"(d) : "l"(a), "l"(b), "l"(c))

__device__ __forceinline__ float f32x2_hsum(ull v) {
    unsigned int lo, hi;
    asm("mov.b64 {%0, %1}, %2;" : "=r"(lo), "=r"(hi) : "l"(v));
    return __uint_as_float(lo) + __uint_as_float(hi);
}

__device__ float  g_cent[KC * DIM];
__device__ float4 g_centT[16 * KCP];     // [chunk j][centroid c] transposed
__device__ float  g_csq[KCP];
__device__ float  g_move[KC];
__device__ unsigned int g_maxmove[2];
__device__ float  g_sums[KC * DIM];      // incremental — never reset
__device__ float  g_cnts[KC];
__device__ float  g_esq[NP];
__device__ float  g_ub[NP];
__device__ float  g_lb[NP];
__device__ int    g_idx[NP];
__device__ int    g_changed[2];
__device__ unsigned int g_bar_cnt;
__device__ volatile unsigned int g_bar_gen;

__device__ __forceinline__ void grid_sync() {
    __syncthreads();
    if (threadIdx.x == 0) {
        __threadfence();
        unsigned int gen = g_bar_gen;
        if (atomicAdd(&g_bar_cnt, 1u) == gridDim.x - 1u) {
            g_bar_cnt = 0u;
            __threadfence();
            g_bar_gen = gen + 1u;
        } else {
            while (g_bar_gen == gen) { __nanosleep(32); }
        }
        __threadfence();
    }
    __syncthreads();
}

__global__ void __launch_bounds__(TPB, 1)
kmeans_persistent_kernel(const float* __restrict__ embeds,
                         const float* __restrict__ init_cent,
                         float* __restrict__ out)
{
    extern __shared__ float s_dyn[];
    float* s_cent = s_dyn;                    // KC*DIM
    float* s_csq  = s_cent + KC * DIM;        // KC
    float* s_bv0  = s_csq + KC;               // 128 merge: pt0 best v
    float* s_sv0  = s_bv0 + 128;              // 128 pt0 second v
    float* s_bv1  = s_sv0 + 128;              // 128 pt1 best v
    float* s_sv1  = s_bv1 + 128;              // 128 pt1 second v
    int*   s_bi0  = (int*)(s_sv1 + 128);      // 128
    int*   s_bi1  = s_bi0 + 128;              // 128
    int*   s_q    = s_bi1 + 128;              // QCAP
    int*   s_qn   = s_q + QCAP;               // 1

    const int tid  = threadIdx.x;
    const int gtid = blockIdx.x * TPB + tid;
    const int nth  = gridDim.x * TPB;
    const int G    = gridDim.x;

    const int half = tid >> 7;
    const int ht   = tid & 127;
    const int p0   = blockIdx.x + G * (2 * ht);
    const int p1   = blockIdx.x + G * (2 * ht + 1);
    const bool v0  = (p0 < NP);
    const bool v1  = (p1 < NP);
    const int kbase = half * HKC;

    // ---------------- init ----------------
    for (int i = gtid; i < KC * DIM; i += nth) {
        g_cent[i] = init_cent[i];
        g_sums[i] = 0.f;
    }
    for (int k = gtid; k < KC; k += nth) {
        g_cnts[k] = 0.f;
        float s = 0.f;
        #pragma unroll 8
        for (int d = 0; d < DIM; ++d) {
            float c = init_cent[k * DIM + d];
            s = fmaf(c, c, s);
        }
        g_csq[k] = s;
        g_move[k] = 0.f;
    }
    for (int i = gtid; i < NP; i += nth) {
        g_idx[i] = -1;
        g_ub[i] = BIGF;
        g_lb[i] = -BIGF;
    }
    if (gtid == 0) {
        g_changed[0] = 0; g_changed[1] = 0;
        g_maxmove[0] = 0u; g_maxmove[1] = 0u;
    }

    // points resident in registers
    ulonglong2 e0[16], e1[16];
    float esq0 = 0.f, esq1 = 0.f;
    if (v0) {
        const ulonglong2* ep = (const ulonglong2*)(embeds + (size_t)p0 * DIM);
        #pragma unroll
        for (int j = 0; j < 16; ++j) e0[j] = ep[j];
        #pragma unroll
        for (int j = 0; j < 16; ++j) {
            float4 v = *(float4*)&e0[j];
            esq0 = fmaf(v.x, v.x, fmaf(v.y, v.y, fmaf(v.z, v.z, fmaf(v.w, v.w, esq0))));
        }
        if (half == 0) g_esq[p0] = esq0;
    }
    if (v1) {
        const ulonglong2* ep = (const ulonglong2*)(embeds + (size_t)p1 * DIM);
        #pragma unroll
        for (int j = 0; j < 16; ++j) e1[j] = ep[j];
        #pragma unroll
        for (int j = 0; j < 16; ++j) {
            float4 v = *(float4*)&e1[j];
            esq1 = fmaf(v.x, v.x, fmaf(v.y, v.y, fmaf(v.z, v.z, fmaf(v.w, v.w, esq1))));
        }
        if (half == 0) g_esq[p1] = esq1;
    } else {
        #pragma unroll
        for (int j = 0; j < 16; ++j) { e1[j].x = 0ull; e1[j].y = 0ull; }
    }

    grid_sync();

    for (int iter = 0; iter < MAX_ITERS; ++iter) {
        // -------- step A: bound update + scan queue (half 0 owns points) ----
        if (tid == 0) *s_qn = 0;
        __syncthreads();

        if (half == 0 && v0) {
            float mm = __uint_as_float(g_maxmove[iter & 1]);
            // point 0
            {
                int a = g_idx[p0];
                bool need = true;
                if (a >= 0) {
                    float ub = g_ub[p0] + fmaf(g_move[a], 1.000002f, DRIFT);
                    float lb = g_lb[p0] - fmaf(mm, 1.000002f, DRIFT);
                    g_ub[p0] = ub; g_lb[p0] = lb;
                    need = !(ub < lb);
                }
                if (need) { int qi = atomicAdd(s_qn, 1); if (qi < QCAP) s_q[qi] = p0; }
            }
            if (v1) {
                int a = g_idx[p1];
                bool need = true;
                if (a >= 0) {
                    float ub = g_ub[p1] + fmaf(g_move[a], 1.000002f, DRIFT);
                    float lb = g_lb[p1] - fmaf(mm, 1.000002f, DRIFT);
                    g_ub[p1] = ub; g_lb[p1] = lb;
                    need = !(ub < lb);
                }
                if (need) { int qi = atomicAdd(s_qn, 1); if (qi < QCAP) s_q[qi] = p1; }
            }
        }
        __syncthreads();
        const int qn = *s_qn;
        const bool fullmode = (qn >= QTHRESH);

        if (fullmode) {
            // ---- stage centroids + csq ----
            for (int i = tid * 4; i < KC * DIM; i += TPB * 4)
                *(float4*)(s_cent + i) = *(const float4*)(g_cent + i);
            for (int i = tid; i < KC; i += TPB)
                s_csq[i] = g_csq[i];
            __syncthreads();

            float b0v = BIGF, s0v = BIGF, b1v = BIGF, s1v = BIGF;
            int   b0i = kbase, b1i = kbase;

            if (v0) {
                #pragma unroll 1
                for (int kk = 0; kk < HKC; kk += 2) {
                    const int k = kbase + kk;
                    const ulonglong2* c0 = (const ulonglong2*)(s_cent + (k + 0) * DIM);
                    const ulonglong2* c1 = (const ulonglong2*)(s_cent + (k + 1) * DIM);
                    ull a00 = 0, b00 = 0, a01 = 0, b01 = 0;
                    ull a10 = 0, b10 = 0, a11 = 0, b11 = 0;
                    #pragma unroll
                    for (int j = 0; j < 16; ++j) {
                        ulonglong2 x0 = c0[j];
                        ulonglong2 x1 = c1[j];
                        ulonglong2 u = e0[j];
                        ulonglong2 w = e1[j];
                        FMA2(a00, u.x, x0.x, a00);
                        FMA2(b00, u.y, x0.y, b00);
                        FMA2(a01, u.x, x1.x, a01);
                        FMA2(b01, u.y, x1.y, b01);
                        FMA2(a10, w.x, x0.x, a10);
                        FMA2(b10, w.y, x0.y, b10);
                        FMA2(a11, w.x, x1.x, a11);
                        FMA2(b11, w.y, x1.y, b11);
                    }
                    float cs0 = s_csq[k + 0];
                    float cs1 = s_csq[k + 1];
                    float d00 = fmaf(-2.f, f32x2_hsum(a00) + f32x2_hsum(b00), cs0);
                    float d01 = fmaf(-2.f, f32x2_hsum(a01) + f32x2_hsum(b01), cs1);
                    float d10 = fmaf(-2.f, f32x2_hsum(a10) + f32x2_hsum(b10), cs0);
                    float d11 = fmaf(-2.f, f32x2_hsum(a11) + f32x2_hsum(b11), cs1);
                    if (d00 < b0v) { s0v = b0v; b0v = d00; b0i = k; }
                    else if (d00 < s0v) s0v = d00;
                    if (d01 < b0v) { s0v = b0v; b0v = d01; b0i = k + 1; }
                    else if (d01 < s0v) s0v = d01;
                    if (d10 < b1v) { s1v = b1v; b1v = d10; b1i = k; }
                    else if (d10 < s1v) s1v = d10;
                    if (d11 < b1v) { s1v = b1v; b1v = d11; b1i = k + 1; }
                    else if (d11 < s1v) s1v = d11;
                }
            }

            // merge halves (upper ks strictly larger -> strict < keeps first-min)
            if (half == 1 && v0) {
                s_bv0[ht] = b0v; s_sv0[ht] = s0v; s_bi0[ht] = b0i;
                s_bv1[ht] = b1v; s_sv1[ht] = s1v; s_bi1[ht] = b1i;
            }
            __syncthreads();

            if (half == 0 && v0) {
                // pt0
                float ubv = s_bv0[ht], usv = s_sv0[ht];
                int   ubi = s_bi0[ht];
                int best0; float bd0, sd0;
                if (ubv < b0v) { best0 = ubi; bd0 = ubv; sd0 = fminf(b0v, usv); }
                else           { best0 = b0i; bd0 = b0v; sd0 = fminf(ubv, s0v); }
                // pt1
                int best1 = 0; float bd1 = 0.f, sd1 = 0.f;
                if (v1) {
                    float uv = s_bv1[ht], us = s_sv1[ht];
                    int   ui = s_bi1[ht];
                    if (uv < b1v) { best1 = ui;  bd1 = uv;  sd1 = fminf(b1v, us); }
                    else          { best1 = b1i; bd1 = b1v; sd1 = fminf(uv, s1v); }
                }

                int old0 = g_idx[p0];
                int old1 = v1 ? g_idx[p1] : -2;
                bool ch0 = (old0 != best0);
                bool ch1 = v1 && (old1 != best1);

                unsigned int am  = __activemask();
                unsigned int bal = __ballot_sync(am, ch0 || ch1);
                int leader = __ffs(am) - 1;
                if (bal && ((int)(tid & 31) == leader))
                    atomicOr(&g_changed[iter & 1], 1);

                if (ch0) {
                    if (old0 >= 0) {
                        float* sp = g_sums + old0 * DIM;
                        #pragma unroll
                        for (int j = 0; j < 16; ++j) {
                            float4 v = *(float4*)&e0[j];
                            atomicAdd((float4*)(sp + 4 * j),
                                      make_float4(-v.x, -v.y, -v.z, -v.w));
                        }
                        atomicAdd(&g_cnts[old0], -1.0f);
                    }
                    float* sp = g_sums + best0 * DIM;
                    #pragma unroll
                    for (int j = 0; j < 16; ++j)
                        atomicAdd((float4*)(sp + 4 * j), *(float4*)&e0[j]);
                    atomicAdd(&g_cnts[best0], 1.0f);
                    g_idx[p0] = best0;
                }
                if (ch1) {
                    if (old1 >= 0) {
                        float* sp = g_sums + old1 * DIM;
                        #pragma unroll
                        for (int j = 0; j < 16; ++j) {
                            float4 v = *(float4*)&e1[j];
                            atomicAdd((float4*)(sp + 4 * j),
                                      make_float4(-v.x, -v.y, -v.z, -v.w));
                        }
                        atomicAdd(&g_cnts[old1], -1.0f);
                    }
                    float* sp = g_sums + best1 * DIM;
                    #pragma unroll
                    for (int j = 0; j < 16; ++j)
                        atomicAdd((float4*)(sp + 4 * j), *(float4*)&e1[j]);
                    atomicAdd(&g_cnts[best1], 1.0f);
                    g_idx[p1] = best1;
                }

                // fresh bounds (true distances)
                {
                    float db = sqrtf(fmaxf(bd0 + esq0, 0.f));
                    float ds = sqrtf(fmaxf(sd0 + esq0, 0.f));
                    g_ub[p0] = db + SLACK_SET;
                    g_lb[p0] = ds - SLACK_SET;
                }
                if (v1) {
                    float db = sqrtf(fmaxf(bd1 + esq1, 0.f));
                    float ds = sqrtf(fmaxf(sd1 + esq1, 0.f));
                    g_ub[p1] = db + SLACK_SET;
                    g_lb[p1] = ds - SLACK_SET;
                }
            }
        } else if (qn > 0) {
            // -------- queue mode: one warp per queued point, lane=centroid ----
            const int w    = tid >> 5;
            const int lane = tid & 31;
            for (int q = w; q < qn; q += 8) {
                const int p = s_q[q];
                const float4* pp = (const float4*)(embeds) + (size_t)p * 16;
                float4 pe[16];
                #pragma unroll
                for (int j = 0; j < 16; ++j) pe[j] = pp[j];
                const float esq = g_esq[p];

                float bv = BIGF, sv = BIGF;
                int   bi = 0;
                #pragma unroll 1
                for (int pass = 0; pass < 16; ++pass) {
                    const int c = (pass << 5) + lane;
                    float aa = 0.f, bb = 0.f;
                    #pragma unroll
                    for (int j = 0; j < 16; ++j) {
                        float4 x = g_centT[(j << 9) + c];
                        float4 u = pe[j];
                        aa = fmaf(u.x, x.x, aa);
                        bb = fmaf(u.y, x.y, bb);
                        aa = fmaf(u.z, x.z, aa);
                        bb = fmaf(u.w, x.w, bb);
                    }
                    float v = (c < KC) ? fmaf(-2.f, aa + bb, g_csq[c]) : BIGF;
                    if (v < bv) { sv = bv; bv = v; bi = c; }
                    else if (v < sv) sv = v;
                }
                // butterfly reduce (best,idx,second) with first-min tie rule
                #pragma unroll
                for (int off = 16; off > 0; off >>= 1) {
                    float ov = __shfl_xor_sync(0xFFFFFFFFu, bv, off);
                    float os = __shfl_xor_sync(0xFFFFFFFFu, sv, off);
                    int   oi = __shfl_xor_sync(0xFFFFFFFFu, bi, off);
                    bool take = (ov < bv) || (ov == bv && oi < bi);
                    float loser = take ? bv : ov;
                    float ns = fminf(fminf(sv, os), loser);
                    if (take) { bv = ov; bi = oi; }
                    sv = ns;
                }

                const int old = g_idx[p];
                if (old != bi) {
                    if (lane == 0) atomicOr(&g_changed[iter & 1], 1);
                    if (lane < 16) {
                        float4 v = pp[lane];
                        atomicAdd((float4*)(g_sums + old * DIM + 4 * lane),
                                  make_float4(-v.x, -v.y, -v.z, -v.w));
                        atomicAdd((float4*)(g_sums + bi * DIM + 4 * lane), v);
                    } else if (lane == 16) {
                        atomicAdd(&g_cnts[old], -1.0f);
                        atomicAdd(&g_cnts[bi], 1.0f);
                    }
                    if (lane == 17) g_idx[p] = bi;
                }
                if (lane == 18) {
                    float db = sqrtf(fmaxf(bv + esq, 0.f));
                    float ds = sqrtf(fmaxf(sv + esq, 0.f));
                    g_ub[p] = db + SLACK_SET;
                    g_lb[p] = ds - SLACK_SET;
                }
            }
        }

        grid_sync();

        // -------- phase 3: centroid update + move tracking ----
        {
            const int w    = tid >> 5;
            const int lane = tid & 31;
            const int k    = blockIdx.x + G * w;    // w<4 covers all KC
            if (w < 4 && k < KC && lane < 16) {
                float cnt = g_cnts[k];
                float den = cnt + EPSV;
                float4 s   = *(float4*)(g_sums + k * DIM + 4 * lane);
                float4 old = *(float4*)(g_cent + k * DIM + 4 * lane);
                float4 c;
                c.x = s.x / den; c.y = s.y / den;
                c.z = s.z / den; c.w = s.w / den;
                *(float4*)(g_cent + k * DIM + 4 * lane) = c;
                g_centT[(lane << 9) + k] = c;
                float csq = fmaf(c.x, c.x, fmaf(c.y, c.y, fmaf(c.z, c.z, c.w * c.w)));
                float dx = c.x - old.x, dy = c.y - old.y;
                float dz = c.z - old.z, dw = c.w - old.w;
                float mv2 = fmaf(dx, dx, fmaf(dy, dy, fmaf(dz, dz, dw * dw)));
                #pragma unroll
                for (int off = 8; off > 0; off >>= 1) {
                    csq += __shfl_down_sync(0xFFFFu, csq, off);
                    mv2 += __shfl_down_sync(0xFFFFu, mv2, off);
                }
                if (lane == 0) {
                    g_csq[k] = csq;
                    float mv = sqrtf(mv2);
                    g_move[k] = mv;
                    if (mv > 0.f)
                        atomicMax(&g_maxmove[(iter + 1) & 1], __float_as_uint(mv));
                }
            }
        }

        int ch = g_changed[iter & 1];
        if (gtid == 0) {
            g_changed[(iter & 1) ^ 1] = 0;
            g_maxmove[iter & 1] = 0u;   // re-zero for reuse at iter+2
        }

        grid_sync();

        if (ch == 0 && iter > 0) break;   // assignment fixed point
    }

    // -------- outputs: centroids [KC*DIM], idxs [NP] (float), counts [KC] ----
    for (int i = gtid; i < KC * DIM; i += nth)
        out[i] = g_cent[i];
    for (int i = gtid; i < NP; i += nth)
        out[KC * DIM + i] = (float)g_idx[i];
    for (int i = gtid; i < KC; i += nth)
        out[KC * DIM + NP + i] = g_cnts[i];
}

extern "C" void kernel_launch(void* const* d_in, const int* in_sizes, int n_in,
                              void* d_out, int out_size)
{
    const float* embeds = (const float*)d_in[0];
    const float* initc  = (const float*)d_in[1];
    if (n_in >= 2 && in_sizes[0] == KC * DIM && in_sizes[1] == NP * DIM) {
        embeds = (const float*)d_in[1];
        initc  = (const float*)d_in[0];
    }
    float* out = (float*)d_out;

    int dev = 0;
    cudaGetDevice(&dev);
    int nsm = 0;
    cudaDeviceGetAttribute(&nsm, cudaDevAttrMultiProcessorCount, dev);

    size_t smem = (size_t)(KC * DIM + KC) * sizeof(float)
                + 128 * 4 * sizeof(float)        // merge value arrays
                + 128 * 2 * sizeof(int)          // merge index arrays
                + (QCAP + 1) * sizeof(int);      // queue
    cudaFuncSetAttribute(kmeans_persistent_kernel,
                         cudaFuncAttributeMaxDynamicSharedMemorySize, (int)smem);

    kmeans_persistent_kernel<<<nsm, TPB, smem>>>(embeds, initc, out);
}

// round 11
// speedup vs baseline: 1.0857x; 1.0857x over previous
#include <cuda_runtime.h>

// KMeans N=30000, D=64, K=500. Persistent kernel, early exit at fixed point.
// R9: SMEM-tiled distance GEMM (points resident in SMEM, centroids staged
// transposed) with 8pt x 4cent register tiles and packed f32x2 FMAs.
// Replaces the broadcast-LDS scan (which wasted 32x crossbar bandwidth:
// 4 cyc per LDS.128 for 16 useful bytes). Distinct-address tiles deliver
// 256B+ useful per instruction -> FMA-bound.

#define NP        30000
#define DIM       64
#define KC        500
#define KCP       512          // padded K
#define MAX_ITERS 1000
#define EPSV      1e-6f
#define TPB       256
#define PSLOT     256          // padded point slots per block
#define BIGF      3.0e38f

typedef unsigned long long ull;

#define FMA2(d, a, b, c) \
    asm("fma.rn.f32x2 %0, %1, %2, %3;" : "=l"(d) : "l"(a), "l"(b), "l"(c))

__device__ __forceinline__ float f32x2_hsum(ull v) {
    unsigned int lo, hi;
    asm("mov.b64 {%0, %1}, %2;" : "=r"(lo), "=r"(hi) : "l"(v));
    return __uint_as_float(lo) + __uint_as_float(hi);
}

__device__ float  g_cent[KC * DIM];      // row-major (for output + phase3)
__device__ float4 g_centT4[16 * KCP];    // [chunk j][cent c] transposed
__device__ float  g_csq[KCP];            // pads = BIGF (never win argmin)
__device__ float  g_sums[KC * DIM];
__device__ float  g_cnts[KC];
__device__ float  g_cnts_out[KC];
__device__ int    g_idx[NP];
__device__ int    g_changed[2];
__device__ unsigned int g_bar_cnt;
__device__ volatile unsigned int g_bar_gen;

// Sense-reversing grid barrier; grid == #SMs, 1 block/SM (smem-forced).
__device__ __forceinline__ void grid_sync() {
    __syncthreads();
    if (threadIdx.x == 0) {
        __threadfence();
        unsigned int gen = g_bar_gen;
        if (atomicAdd(&g_bar_cnt, 1u) == gridDim.x - 1u) {
            g_bar_cnt = 0u;
            __threadfence();
            g_bar_gen = gen + 1u;
        } else {
            while (g_bar_gen == gen) { __nanosleep(32); }
        }
        __threadfence();
    }
    __syncthreads();
}

__global__ void __launch_bounds__(TPB, 1)
kmeans_persistent_kernel(const float* __restrict__ embeds,
                         const float* __restrict__ init_cent,
                         float* __restrict__ out)
{
    extern __shared__ float s_dyn[];
    float4* s_centT = (float4*)s_dyn;                 // 16*KCP float4 (128KB)
    float4* s_pts   = s_centT + 16 * KCP;             // 16*PSLOT float4 (64KB)
    float*  s_csq   = (float*)(s_pts + 16 * PSLOT);   // KCP floats
    int*    s_best  = (int*)(s_csq + KCP);            // PSLOT ints

    const int tid  = threadIdx.x;
    const int b    = blockIdx.x;
    const int G    = gridDim.x;
    const int gtid = b * TPB + tid;
    const int nth  = G * TPB;
    const int ty   = tid >> 4;          // 0..15  (owns points pp*16+ty)
    const int tx   = tid & 15;          // 0..15  (owns cents cc*16+tx)

    // ---------------- init ----------------
    for (int i = gtid; i < KC * DIM; i += nth) {
        g_cent[i] = init_cent[i];
        g_sums[i] = 0.f;
    }
    for (int k = gtid; k < KCP; k += nth) {
        if (k < KC) {
            g_cnts[k] = 0.f;
            float s = 0.f;
            #pragma unroll 8
            for (int d = 0; d < DIM; ++d) {
                float c = init_cent[k * DIM + d];
                s = fmaf(c, c, s);
            }
            g_csq[k] = s;
        } else {
            g_csq[k] = BIGF;   // padded centroids can never win
        }
    }
    for (int i = gtid; i < 16 * KCP; i += nth) {
        int j = i >> 9, c = i & (KCP - 1);
        g_centT4[i] = (c < KC) ? *(const float4*)(init_cent + c * DIM + 4 * j)
                               : make_float4(0.f, 0.f, 0.f, 0.f);
    }
    for (int i = gtid; i < NP; i += nth) g_idx[i] = -1;
    if (gtid == 0) { g_changed[0] = 0; g_changed[1] = 0; }

    // ---- load this block's points into SMEM (transposed, once) ----
    // slot i  <->  global point p = b + G*i
    const int npts = (NP - 1 - b) / G + 1;   // 197 or 198
    {
        const int i = tid;                    // PSLOT == TPB
        const int p = b + G * i;
        const bool v = (i < npts);
        const float4* ep = (const float4*)embeds + (size_t)p * 16;
        #pragma unroll
        for (int j = 0; j < 16; ++j)
            s_pts[j * PSLOT + i] = v ? ep[j] : make_float4(0.f, 0.f, 0.f, 0.f);
    }

    grid_sync();

    for (int iter = 0; iter < MAX_ITERS; ++iter) {
        // ---- stage transposed centroids + csq into SMEM ----
        for (int i = tid; i < 16 * KCP; i += TPB)
            s_centT[i] = g_centT4[i];
        for (int i = tid; i < KCP; i += TPB)
            s_csq[i] = g_csq[i];
        __syncthreads();

        // ---- distance GEMM + fused argmin ----
        const ulonglong2* cT = (const ulonglong2*)s_centT;
        const ulonglong2* pT = (const ulonglong2*)s_pts;

        #pragma unroll 1
        for (int ptb = 0; ptb < 2; ++ptb) {
            float bv[8];
            int   bi[8];
            #pragma unroll
            for (int pp = 0; pp < 8; ++pp) { bv[pp] = BIGF; bi[pp] = 0; }

            const int pbase = ptb * 128 + ty;   // + pp*16
            #pragma unroll 1
            for (int kb = 0; kb < 8; ++kb) {
                const int cbase = kb * 64 + tx; // + cc*16
                ull acc[8][4];
                #pragma unroll
                for (int pp = 0; pp < 8; ++pp)
                    #pragma unroll
                    for (int cc = 0; cc < 4; ++cc) acc[pp][cc] = 0ull;

                #pragma unroll 4
                for (int j = 0; j < 16; ++j) {
                    ulonglong2 cf[4];
                    #pragma unroll
                    for (int cc = 0; cc < 4; ++cc)
                        cf[cc] = cT[j * KCP + cbase + cc * 16];
                    ulonglong2 pf[8];
                    #pragma unroll
                    for (int pp = 0; pp < 8; ++pp)
                        pf[pp] = pT[j * PSLOT + pbase + pp * 16];
                    #pragma unroll
                    for (int pp = 0; pp < 8; ++pp) {
                        #pragma unroll
                        for (int cc = 0; cc < 4; ++cc) {
                            FMA2(acc[pp][cc], pf[pp].x, cf[cc].x, acc[pp][cc]);
                            FMA2(acc[pp][cc], pf[pp].y, cf[cc].y, acc[pp][cc]);
                        }
                    }
                }
                #pragma unroll
                for (int cc = 0; cc < 4; ++cc) {
                    const int ci = cbase + cc * 16;
                    const float cq = s_csq[ci];
                    #pragma unroll
                    for (int pp = 0; pp < 8; ++pp) {
                        float dot = f32x2_hsum(acc[pp][cc]);
                        float d = fmaf(-2.f, dot, cq);
                        // argmin with first-index tie rule
                        if (d < bv[pp] || (d == bv[pp] && ci < bi[pp])) {
                            bv[pp] = d; bi[pp] = ci;
                        }
                    }
                }
            }
            // reduce across tx (lanes 0-15 / 16-31 within the warp)
            #pragma unroll
            for (int pp = 0; pp < 8; ++pp) {
                float v = bv[pp];
                int   i2 = bi[pp];
                #pragma unroll
                for (int off = 1; off < 16; off <<= 1) {
                    float ov = __shfl_xor_sync(0xFFFFFFFFu, v, off);
                    int   oi = __shfl_xor_sync(0xFFFFFFFFu, i2, off);
                    if (ov < v || (ov == v && oi < i2)) { v = ov; i2 = oi; }
                }
                if (tx == 0) s_best[ptb * 128 + pp * 16 + ty] = i2;
            }
        }
        __syncthreads();

        // ---- epilogue: one slot per thread ----
        {
            const int p = b + G * tid;
            const bool valid = (tid < npts);
            int best = 0;
            bool ch = false;
            if (valid) {
                best = s_best[tid];
                ch = (g_idx[p] != best);
            }
            unsigned int bal = __ballot_sync(0xFFFFFFFFu, ch);
            if (bal && ((tid & 31) == 0))
                atomicOr(&g_changed[iter & 1], 1);
            if (valid) {
                g_idx[p] = best;
                float* sp = g_sums + best * DIM;
                #pragma unroll
                for (int j = 0; j < 16; ++j)
                    atomicAdd((float4*)(sp + 4 * j), s_pts[j * PSLOT + tid]);
                atomicAdd(&g_cnts[best], 1.0f);
            }
        }

        grid_sync();

        // ---- phase 3: centroid update, one k per (block, warp) ----
        {
            const int w    = tid >> 5;
            const int lane = tid & 31;
            const int k    = b + G * w;          // w<4 covers k<608 >= KC
            if (w < 4 && k < KC && lane < 16) {
                float cnt = g_cnts[k];
                float den = cnt + EPSV;
                float4 s = *(float4*)(g_sums + k * DIM + 4 * lane);
                float4 c;
                c.x = s.x / den; c.y = s.y / den;
                c.z = s.z / den; c.w = s.w / den;
                *(float4*)(g_sums + k * DIM + 4 * lane) = make_float4(0.f, 0.f, 0.f, 0.f);
                *(float4*)(g_cent + k * DIM + 4 * lane) = c;
                g_centT4[lane * KCP + k] = c;
                float csq = fmaf(c.x, c.x, fmaf(c.y, c.y, fmaf(c.z, c.z, c.w * c.w)));
                #pragma unroll
                for (int off = 8; off > 0; off >>= 1)
                    csq += __shfl_down_sync(0xFFFFu, csq, off);
                if (lane == 0) {
                    g_csq[k] = csq;
                    g_cnts_out[k] = cnt;
                    g_cnts[k] = 0.f;
                }
            }
        }

        int ch = g_changed[iter & 1];
        if (gtid == 0) g_changed[(iter & 1) ^ 1] = 0;

        grid_sync();

        if (ch == 0 && iter > 0) break;   // assignment fixed point
    }

    // ---- outputs: centroids [KC*DIM], idxs [NP] (float), counts [KC] ----
    for (int i = gtid; i < KC * DIM; i += nth)
        out[i] = g_cent[i];
    for (int i = gtid; i < NP; i += nth)
        out[KC * DIM + i] = (float)g_idx[i];
    for (int i = gtid; i < KC; i += nth)
        out[KC * DIM + NP + i] = g_cnts_out[i];
}

extern "C" void kernel_launch(void* const* d_in, const int* in_sizes, int n_in,
                              void* d_out, int out_size)
{
    const float* embeds = (const float*)d_in[0];
    const float* initc  = (const float*)d_in[1];
    if (n_in >= 2 && in_sizes[0] == KC * DIM && in_sizes[1] == NP * DIM) {
        embeds = (const float*)d_in[1];
        initc  = (const float*)d_in[0];
    }
    float* out = (float*)d_out;

    int dev = 0;
    cudaGetDevice(&dev);
    int nsm = 0;
    cudaDeviceGetAttribute(&nsm, cudaDevAttrMultiProcessorCount, dev);

    size_t smem = (size_t)(16 * KCP + 16 * PSLOT) * sizeof(float4)
                + KCP * sizeof(float) + PSLOT * sizeof(int);   // ~199.7 KB
    cudaFuncSetAttribute(kmeans_persistent_kernel,
                         cudaFuncAttributeMaxDynamicSharedMemorySize, (int)smem);

    kmeans_persistent_kernel<<<nsm, TPB, smem>>>(embeds, initc, out);
}

// round 13
// speedup vs baseline: 1.2696x; 1.1694x over previous
#include <cuda_runtime.h>

// KMeans N=30000, D=64, K=500. Persistent kernel, early exit at fixed point.
// R12: 8pt x 8cent register tile (LDS:FMA2 = 16:128 per j-chunk -> FMA-bound;
// R9's 8x4 tile was crossbar-bound at 12:64) + incremental cluster sums
// (atomics only on assignment change; steady state ~0 atomic traffic).

#define NP        30000
#define DIM       64
#define KC        500
#define KCP       512          // padded K
#define MAX_ITERS 1000
#define EPSV      1e-6f
#define TPB       256
#define PSLOT     256          // padded point slots per block
#define BIGF      3.0e38f

typedef unsigned long long ull;

#define FMA2(d, a, b, c) \
    asm("fma.rn.f32x2 %0, %1, %2, %3;" : "=l"(d) : "l"(a), "l"(b), "l"(c))

__device__ __forceinline__ float f32x2_hsum(ull v) {
    unsigned int lo, hi;
    asm("mov.b64 {%0, %1}, %2;" : "=r"(lo), "=r"(hi) : "l"(v));
    return __uint_as_float(lo) + __uint_as_float(hi);
}

__device__ float  g_cent[KC * DIM];      // row-major (output + phase3)
__device__ float4 g_centT4[16 * KCP];    // [chunk j][cent c] transposed
__device__ float  g_csq[KCP];            // pads = BIGF
__device__ float  g_sums[KC * DIM];      // incremental (reset only at launch)
__device__ float  g_cnts[KC];            // incremental
__device__ int    g_idx[NP];
__device__ int    g_changed[2];
__device__ unsigned int g_bar_cnt;
__device__ volatile unsigned int g_bar_gen;

// Sense-reversing grid barrier; grid == #SMs, 1 block/SM (smem-forced).
__device__ __forceinline__ void grid_sync() {
    __syncthreads();
    if (threadIdx.x == 0) {
        __threadfence();
        unsigned int gen = g_bar_gen;
        if (atomicAdd(&g_bar_cnt, 1u) == gridDim.x - 1u) {
            g_bar_cnt = 0u;
            __threadfence();
            g_bar_gen = gen + 1u;
        } else {
            while (g_bar_gen == gen) { __nanosleep(32); }
        }
        __threadfence();
    }
    __syncthreads();
}

__global__ void __launch_bounds__(TPB, 1)
kmeans_persistent_kernel(const float* __restrict__ embeds,
                         const float* __restrict__ init_cent,
                         float* __restrict__ out)
{
    extern __shared__ float s_dyn[];
    float4* s_centT = (float4*)s_dyn;                 // 16*KCP float4 (128KB)
    float4* s_pts   = s_centT + 16 * KCP;             // 16*PSLOT float4 (64KB)
    float*  s_csq   = (float*)(s_pts + 16 * PSLOT);   // KCP floats
    int*    s_best  = (int*)(s_csq + KCP);            // PSLOT ints

    const int tid  = threadIdx.x;
    const int b    = blockIdx.x;
    const int G    = gridDim.x;
    const int gtid = b * TPB + tid;
    const int nth  = G * TPB;
    const int ty   = tid >> 4;          // 0..15  (points pp*16+ty)
    const int tx   = tid & 15;          // 0..15  (cents cc*16+tx)

    // ---------------- init (fresh every launch: deterministic) ----------------
    for (int i = gtid; i < KC * DIM; i += nth) {
        g_cent[i] = init_cent[i];
        g_sums[i] = 0.f;
    }
    for (int k = gtid; k < KCP; k += nth) {
        if (k < KC) {
            g_cnts[k] = 0.f;
            float s = 0.f;
            #pragma unroll 8
            for (int d = 0; d < DIM; ++d) {
                float c = init_cent[k * DIM + d];
                s = fmaf(c, c, s);
            }
            g_csq[k] = s;
        } else {
            g_csq[k] = BIGF;
        }
    }
    for (int i = gtid; i < 16 * KCP; i += nth) {
        int j = i >> 9, c = i & (KCP - 1);
        g_centT4[i] = (c < KC) ? *(const float4*)(init_cent + c * DIM + 4 * j)
                               : make_float4(0.f, 0.f, 0.f, 0.f);
    }
    for (int i = gtid; i < NP; i += nth) g_idx[i] = -1;
    if (gtid == 0) { g_changed[0] = 0; g_changed[1] = 0; }

    // ---- this block's points -> SMEM transposed (once; slot i <-> p=b+G*i) ----
    const int npts = (NP - 1 - b) / G + 1;   // 197 or 198
    {
        const int i = tid;                    // PSLOT == TPB
        const int p = b + G * i;
        const bool v = (i < npts);
        const float4* ep = (const float4*)embeds + (size_t)p * 16;
        #pragma unroll
        for (int j = 0; j < 16; ++j)
            s_pts[j * PSLOT + i] = v ? ep[j] : make_float4(0.f, 0.f, 0.f, 0.f);
    }

    grid_sync();

    for (int iter = 0; iter < MAX_ITERS; ++iter) {
        // ---- stage transposed centroids + csq ----
        for (int i = tid; i < 16 * KCP; i += TPB)
            s_centT[i] = g_centT4[i];
        for (int i = tid; i < KCP; i += TPB)
            s_csq[i] = g_csq[i];
        __syncthreads();

        // ---- distance GEMM (8pt x 8cent per thread) + fused argmin ----
        const ulonglong2* cT = (const ulonglong2*)s_centT;
        const ulonglong2* pT = (const ulonglong2*)s_pts;

        #pragma unroll 1
        for (int ptb = 0; ptb < 2; ++ptb) {
            float bv[8];
            int   bi[8];
            #pragma unroll
            for (int pp = 0; pp < 8; ++pp) { bv[pp] = BIGF; bi[pp] = 0; }

            const int pbase = ptb * 128 + ty;    // + pp*16
            #pragma unroll 1
            for (int kb = 0; kb < 4; ++kb) {
                const int cbase = kb * 128 + tx; // + cc*16
                ull acc[8][8];
                #pragma unroll
                for (int pp = 0; pp < 8; ++pp)
                    #pragma unroll
                    for (int cc = 0; cc < 8; ++cc) acc[pp][cc] = 0ull;

                #pragma unroll 1
                for (int j = 0; j < 16; ++j) {
                    ulonglong2 cf[8];
                    #pragma unroll
                    for (int cc = 0; cc < 8; ++cc)
                        cf[cc] = cT[j * KCP + cbase + cc * 16];
                    ulonglong2 pf[8];
                    #pragma unroll
                    for (int pp = 0; pp < 8; ++pp)
                        pf[pp] = pT[j * PSLOT + pbase + pp * 16];
                    #pragma unroll
                    for (int pp = 0; pp < 8; ++pp) {
                        #pragma unroll
                        for (int cc = 0; cc < 8; ++cc) {
                            FMA2(acc[pp][cc], pf[pp].x, cf[cc].x, acc[pp][cc]);
                            FMA2(acc[pp][cc], pf[pp].y, cf[cc].y, acc[pp][cc]);
                        }
                    }
                }
                #pragma unroll
                for (int cc = 0; cc < 8; ++cc) {
                    const int ci = cbase + cc * 16;
                    const float cq = s_csq[ci];
                    #pragma unroll
                    for (int pp = 0; pp < 8; ++pp) {
                        float d = fmaf(-2.f, f32x2_hsum(acc[pp][cc]), cq);
                        // argmin with first-index tie rule
                        if (d < bv[pp] || (d == bv[pp] && ci < bi[pp])) {
                            bv[pp] = d; bi[pp] = ci;
                        }
                    }
                }
            }
            // reduce across the 16 tx lanes (two independent halves per warp)
            #pragma unroll
            for (int pp = 0; pp < 8; ++pp) {
                float v = bv[pp];
                int   i2 = bi[pp];
                #pragma unroll
                for (int off = 1; off < 16; off <<= 1) {
                    float ov = __shfl_xor_sync(0xFFFFFFFFu, v, off);
                    int   oi = __shfl_xor_sync(0xFFFFFFFFu, i2, off);
                    if (ov < v || (ov == v && oi < i2)) { v = ov; i2 = oi; }
                }
                if (tx == 0) s_best[ptb * 128 + pp * 16 + ty] = i2;
            }
        }
        __syncthreads();

        // ---- epilogue: incremental sums (atomics only on change) ----
        {
            const int p = b + G * tid;
            const bool valid = (tid < npts);
            int best = 0, old = -2;
            bool ch = false;
            if (valid) {
                best = s_best[tid];
                old = g_idx[p];
                ch = (old != best);
            }
            unsigned int bal = __ballot_sync(0xFFFFFFFFu, ch);
            if (bal && ((tid & 31) == 0))
                atomicOr(&g_changed[iter & 1], 1);
            if (ch) {
                if (old >= 0) {
                    float* sp = g_sums + old * DIM;
                    #pragma unroll
                    for (int j = 0; j < 16; ++j) {
                        float4 v = s_pts[j * PSLOT + tid];
                        atomicAdd((float4*)(sp + 4 * j),
                                  make_float4(-v.x, -v.y, -v.z, -v.w));
                    }
                    atomicAdd(&g_cnts[old], -1.0f);
                }
                float* sp = g_sums + best * DIM;
                #pragma unroll
                for (int j = 0; j < 16; ++j)
                    atomicAdd((float4*)(sp + 4 * j), s_pts[j * PSLOT + tid]);
                atomicAdd(&g_cnts[best], 1.0f);
                g_idx[p] = best;
            }
        }

        grid_sync();

        // ---- phase 3: centroid update from persistent sums ----
        {
            const int w    = tid >> 5;
            const int lane = tid & 31;
            const int k    = b + G * w;          // w<4 covers k<608 >= KC
            if (w < 4 && k < KC && lane < 16) {
                float cnt = g_cnts[k];
                float den = cnt + EPSV;
                float4 s = *(float4*)(g_sums + k * DIM + 4 * lane);
                float4 c;
                c.x = s.x / den; c.y = s.y / den;
                c.z = s.z / den; c.w = s.w / den;
                *(float4*)(g_cent + k * DIM + 4 * lane) = c;
                g_centT4[lane * KCP + k] = c;
                float csq = fmaf(c.x, c.x, fmaf(c.y, c.y, fmaf(c.z, c.z, c.w * c.w)));
                #pragma unroll
                for (int off = 8; off > 0; off >>= 1)
                    csq += __shfl_down_sync(0xFFFFu, csq, off);
                if (lane == 0) g_csq[k] = csq;
            }
        }

        int ch = g_changed[iter & 1];
        if (gtid == 0) g_changed[(iter & 1) ^ 1] = 0;

        grid_sync();

        if (ch == 0 && iter > 0) break;   // assignment fixed point
    }

    // ---- outputs: centroids [KC*DIM], idxs [NP] (float), counts [KC] ----
    for (int i = gtid; i < KC * DIM; i += nth)
        out[i] = g_cent[i];
    for (int i = gtid; i < NP; i += nth)
        out[KC * DIM + i] = (float)g_idx[i];
    for (int i = gtid; i < KC; i += nth)
        out[KC * DIM + NP + i] = g_cnts[i];
}

extern "C" void kernel_launch(void* const* d_in, const int* in_sizes, int n_in,
                              void* d_out, int out_size)
{
    const float* embeds = (const float*)d_in[0];
    const float* initc  = (const float*)d_in[1];
    if (n_in >= 2 && in_sizes[0] == KC * DIM && in_sizes[1] == NP * DIM) {
        embeds = (const float*)d_in[1];
        initc  = (const float*)d_in[0];
    }
    float* out = (float*)d_out;

    int dev = 0;
    cudaGetDevice(&dev);
    int nsm = 0;
    cudaDeviceGetAttribute(&nsm, cudaDevAttrMultiProcessorCount, dev);

    size_t smem = (size_t)(16 * KCP + 16 * PSLOT) * sizeof(float4)
                + KCP * sizeof(float) + PSLOT * sizeof(int);   // ~199.7 KB
    cudaFuncSetAttribute(kmeans_persistent_kernel,
                         cudaFuncAttributeMaxDynamicSharedMemorySize, (int)smem);

    kmeans_persistent_kernel<<<nsm, TPB, smem>>>(embeds, initc, out);
}

// round 15
// speedup vs baseline: 1.4940x; 1.1767x over previous
#include <cuda_runtime.h>

// KMeans N=30000, D=64, K=500. Persistent kernel, early exit at fixed point.
// R14: remove dead-slot GEMM work. R12 tiled 256 point slots but only <=198
// are real (22.7% wasted FMAs). Two passes now cover 208 slots: 8 pp-groups
// (slots 0..127) + 5 pp-groups (slots 128..207). Everything else from R12
// (8x8 f32x2 register tile, incremental sums, early exit) unchanged.

#define NP        30000
#define DIM       64
#define KC        500
#define KCP       512          // padded K
#define MAX_ITERS 1000
#define EPSV      1e-6f
#define TPB       256
#define PSLOT     256          // SMEM point slots (only 208 tiled)
#define BIGF      3.0e38f

typedef unsigned long long ull;

#define FMA2(d, a, b, c) \
    asm("fma.rn.f32x2 %0, %1, %2, %3;" : "=l"(d) : "l"(a), "l"(b), "l"(c))

__device__ __forceinline__ float f32x2_hsum(ull v) {
    unsigned int lo, hi;
    asm("mov.b64 {%0, %1}, %2;" : "=r"(lo), "=r"(hi) : "l"(v));
    return __uint_as_float(lo) + __uint_as_float(hi);
}

__device__ float  g_cent[KC * DIM];      // row-major (output + phase3)
__device__ float4 g_centT4[16 * KCP];    // [chunk j][cent c] transposed
__device__ float  g_csq[KCP];            // pads = BIGF
__device__ float  g_sums[KC * DIM];      // incremental
__device__ float  g_cnts[KC];            // incremental
__device__ int    g_idx[NP];
__device__ int    g_changed[2];
__device__ unsigned int g_bar_cnt;
__device__ volatile unsigned int g_bar_gen;

// Sense-reversing grid barrier; grid == #SMs, 1 block/SM (smem-forced).
__device__ __forceinline__ void grid_sync() {
    __syncthreads();
    if (threadIdx.x == 0) {
        __threadfence();
        unsigned int gen = g_bar_gen;
        if (atomicAdd(&g_bar_cnt, 1u) == gridDim.x - 1u) {
            g_bar_cnt = 0u;
            __threadfence();
            g_bar_gen = gen + 1u;
        } else {
            while (g_bar_gen == gen) { __nanosleep(32); }
        }
        __threadfence();
    }
    __syncthreads();
}

// One GEMM+argmin pass over PPN point-groups starting at slotbase.
template<int PPN>
__device__ __forceinline__ void gemm_pass(
    const ulonglong2* __restrict__ cT,
    const ulonglong2* __restrict__ pT,
    const float* __restrict__ s_csq,
    int* __restrict__ s_best,
    const int tx, const int ty, const int slotbase)
{
    float bv[PPN];
    int   bi[PPN];
    #pragma unroll
    for (int pp = 0; pp < PPN; ++pp) { bv[pp] = BIGF; bi[pp] = 0; }

    const int pbase = slotbase + ty;
    #pragma unroll 1
    for (int kb = 0; kb < 4; ++kb) {
        const int cbase = kb * 128 + tx;
        ull acc[PPN][8];
        #pragma unroll
        for (int pp = 0; pp < PPN; ++pp)
            #pragma unroll
            for (int cc = 0; cc < 8; ++cc) acc[pp][cc] = 0ull;

        #pragma unroll 1
        for (int j = 0; j < 16; ++j) {
            ulonglong2 cf[8];
            #pragma unroll
            for (int cc = 0; cc < 8; ++cc)
                cf[cc] = cT[j * KCP + cbase + cc * 16];
            ulonglong2 pf[PPN];
            #pragma unroll
            for (int pp = 0; pp < PPN; ++pp)
                pf[pp] = pT[j * PSLOT + pbase + pp * 16];
            #pragma unroll
            for (int pp = 0; pp < PPN; ++pp) {
                #pragma unroll
                for (int cc = 0; cc < 8; ++cc) {
                    FMA2(acc[pp][cc], pf[pp].x, cf[cc].x, acc[pp][cc]);
                    FMA2(acc[pp][cc], pf[pp].y, cf[cc].y, acc[pp][cc]);
                }
            }
        }
        #pragma unroll
        for (int cc = 0; cc < 8; ++cc) {
            const int ci = cbase + cc * 16;
            const float cq = s_csq[ci];
            #pragma unroll
            for (int pp = 0; pp < PPN; ++pp) {
                float d = fmaf(-2.f, f32x2_hsum(acc[pp][cc]), cq);
                // argmin with first-index tie rule
                if (d < bv[pp] || (d == bv[pp] && ci < bi[pp])) {
                    bv[pp] = d; bi[pp] = ci;
                }
            }
        }
    }
    // reduce across the 16 tx lanes (two independent halves per warp)
    #pragma unroll
    for (int pp = 0; pp < PPN; ++pp) {
        float v = bv[pp];
        int   i2 = bi[pp];
        #pragma unroll
        for (int off = 1; off < 16; off <<= 1) {
            float ov = __shfl_xor_sync(0xFFFFFFFFu, v, off);
            int   oi = __shfl_xor_sync(0xFFFFFFFFu, i2, off);
            if (ov < v || (ov == v && oi < i2)) { v = ov; i2 = oi; }
        }
        if (tx == 0) s_best[slotbase + pp * 16 + ty] = i2;
    }
}

__global__ void __launch_bounds__(TPB, 1)
kmeans_persistent_kernel(const float* __restrict__ embeds,
                         const float* __restrict__ init_cent,
                         float* __restrict__ out)
{
    extern __shared__ float s_dyn[];
    float4* s_centT = (float4*)s_dyn;                 // 16*KCP float4 (128KB)
    float4* s_pts   = s_centT + 16 * KCP;             // 16*PSLOT float4 (64KB)
    float*  s_csq   = (float*)(s_pts + 16 * PSLOT);   // KCP floats
    int*    s_best  = (int*)(s_csq + KCP);            // PSLOT ints

    const int tid  = threadIdx.x;
    const int b    = blockIdx.x;
    const int G    = gridDim.x;
    const int gtid = b * TPB + tid;
    const int nth  = G * TPB;
    const int ty   = tid >> 4;          // 0..15
    const int tx   = tid & 15;          // 0..15

    // ---------------- init (fresh every launch: deterministic) ----------------
    for (int i = gtid; i < KC * DIM; i += nth) {
        g_cent[i] = init_cent[i];
        g_sums[i] = 0.f;
    }
    for (int k = gtid; k < KCP; k += nth) {
        if (k < KC) {
            g_cnts[k] = 0.f;
            float s = 0.f;
            #pragma unroll 8
            for (int d = 0; d < DIM; ++d) {
                float c = init_cent[k * DIM + d];
                s = fmaf(c, c, s);
            }
            g_csq[k] = s;
        } else {
            g_csq[k] = BIGF;
        }
    }
    for (int i = gtid; i < 16 * KCP; i += nth) {
        int j = i >> 9, c = i & (KCP - 1);
        g_centT4[i] = (c < KC) ? *(const float4*)(init_cent + c * DIM + 4 * j)
                               : make_float4(0.f, 0.f, 0.f, 0.f);
    }
    for (int i = gtid; i < NP; i += nth) g_idx[i] = -1;
    if (gtid == 0) { g_changed[0] = 0; g_changed[1] = 0; }

    // ---- this block's points -> SMEM transposed (once; slot i <-> p=b+G*i) ----
    const int npts = (NP - 1 - b) / G + 1;   // 197 or 198 (<= 208 tiled slots)
    {
        const int i = tid;                    // PSLOT == TPB
        const int p = b + G * i;
        const bool v = (i < npts);
        const float4* ep = (const float4*)embeds + (size_t)p * 16;
        #pragma unroll
        for (int j = 0; j < 16; ++j)
            s_pts[j * PSLOT + i] = v ? ep[j] : make_float4(0.f, 0.f, 0.f, 0.f);
    }

    grid_sync();

    for (int iter = 0; iter < MAX_ITERS; ++iter) {
        // ---- stage transposed centroids + csq ----
        for (int i = tid; i < 16 * KCP; i += TPB)
            s_centT[i] = g_centT4[i];
        for (int i = tid; i < KCP; i += TPB)
            s_csq[i] = g_csq[i];
        __syncthreads();

        // ---- distance GEMM + fused argmin over 208 slots (13 pp-groups) ----
        const ulonglong2* cT = (const ulonglong2*)s_centT;
        const ulonglong2* pT = (const ulonglong2*)s_pts;
        gemm_pass<8>(cT, pT, s_csq, s_best, tx, ty, 0);    // slots   0..127
        gemm_pass<5>(cT, pT, s_csq, s_best, tx, ty, 128);  // slots 128..207
        __syncthreads();

        // ---- epilogue: incremental sums (atomics only on change) ----
        {
            const int p = b + G * tid;
            const bool valid = (tid < npts);
            int best = 0, old = -2;
            bool ch = false;
            if (valid) {
                best = s_best[tid];
                old = g_idx[p];
                ch = (old != best);
            }
            unsigned int bal = __ballot_sync(0xFFFFFFFFu, ch);
            if (bal && ((tid & 31) == 0))
                atomicOr(&g_changed[iter & 1], 1);
            if (ch) {
                if (old >= 0) {
                    float* sp = g_sums + old * DIM;
                    #pragma unroll
                    for (int j = 0; j < 16; ++j) {
                        float4 v = s_pts[j * PSLOT + tid];
                        atomicAdd((float4*)(sp + 4 * j),
                                  make_float4(-v.x, -v.y, -v.z, -v.w));
                    }
                    atomicAdd(&g_cnts[old], -1.0f);
                }
                float* sp = g_sums + best * DIM;
                #pragma unroll
                for (int j = 0; j < 16; ++j)
                    atomicAdd((float4*)(sp + 4 * j), s_pts[j * PSLOT + tid]);
                atomicAdd(&g_cnts[best], 1.0f);
                g_idx[p] = best;
            }
        }

        grid_sync();

        // ---- phase 3: centroid update from persistent sums ----
        {
            const int w    = tid >> 5;
            const int lane = tid & 31;
            const int k    = b + G * w;          // w<4 covers k<608 >= KC
            if (w < 4 && k < KC && lane < 16) {
                float cnt = g_cnts[k];
                float den = cnt + EPSV;
                float4 s = *(float4*)(g_sums + k * DIM + 4 * lane);
                float4 c;
                c.x = s.x / den; c.y = s.y / den;
                c.z = s.z / den; c.w = s.w / den;
                *(float4*)(g_cent + k * DIM + 4 * lane) = c;
                g_centT4[lane * KCP + k] = c;
                float csq = fmaf(c.x, c.x, fmaf(c.y, c.y, fmaf(c.z, c.z, c.w * c.w)));
                #pragma unroll
                for (int off = 8; off > 0; off >>= 1)
                    csq += __shfl_down_sync(0xFFFFu, csq, off);
                if (lane == 0) g_csq[k] = csq;
            }
        }

        int ch = g_changed[iter & 1];
        if (gtid == 0) g_changed[(iter & 1) ^ 1] = 0;

        grid_sync();

        if (ch == 0 && iter > 0) break;   // assignment fixed point
    }

    // ---- outputs: centroids [KC*DIM], idxs [NP] (float), counts [KC] ----
    for (int i = gtid; i < KC * DIM; i += nth)
        out[i] = g_cent[i];
    for (int i = gtid; i < NP; i += nth)
        out[KC * DIM + i] = (float)g_idx[i];
    for (int i = gtid; i < KC; i += nth)
        out[KC * DIM + NP + i] = g_cnts[i];
}

extern "C" void kernel_launch(void* const* d_in, const int* in_sizes, int n_in,
                              void* d_out, int out_size)
{
    const float* embeds = (const float*)d_in[0];
    const float* initc  = (const float*)d_in[1];
    if (n_in >= 2 && in_sizes[0] == KC * DIM && in_sizes[1] == NP * DIM) {
        embeds = (const float*)d_in[1];
        initc  = (const float*)d_in[0];
    }
    float* out = (float*)d_out;

    int dev = 0;
    cudaGetDevice(&dev);
    int nsm = 0;
    cudaDeviceGetAttribute(&nsm, cudaDevAttrMultiProcessorCount, dev);

    size_t smem = (size_t)(16 * KCP + 16 * PSLOT) * sizeof(float4)
                + KCP * sizeof(float) + PSLOT * sizeof(int);   // ~199.7 KB
    cudaFuncSetAttribute(kmeans_persistent_kernel,
                         cudaFuncAttributeMaxDynamicSharedMemorySize, (int)smem);

    kmeans_persistent_kernel<<<nsm, TPB, smem>>>(embeds, initc, out);
}

// round 17
// speedup vs baseline: 1.5624x; 1.0458x over previous
#include <cuda_runtime.h>

// KMeans N=30000, D=64, K=500. Persistent kernel, early exit at fixed point.
// R16: single grid barrier per iteration. Centroid update fused into staging
// (each block computes cents = sums * rcp(cnt+eps) into its own SMEM,
// bit-identical across blocks). Dirty-cluster bitmap: staging updates only
// changed clusters (sparse path when <128 dirty). GEMM (8x8 f32x2 tile over
// 208 slots) unchanged from R14 except padded SMEM stride + simpler argmin.

#define NP        30000
#define DIM       64
#define KC        500
#define KCP       512          // padded K (columns)
#define KCS       513          // padded SMEM stride (float4 units) - STS conflicts
#define MAX_ITERS 1000
#define EPSV      1e-6f
#define TPB       256
#define PSLOT     256          // SMEM point slots (208 tiled)
#define BIGF      3.0e38f
#define FULLTH    128          // dirty threshold: full vs sparse restage

typedef unsigned long long ull;

#define FMA2(d, a, b, c) \
    asm("fma.rn.f32x2 %0, %1, %2, %3;" : "=l"(d) : "l"(a), "l"(b), "l"(c))

__device__ __forceinline__ float f32x2_hsum(ull v) {
    unsigned int lo, hi;
    asm("mov.b64 {%0, %1}, %2;" : "=r"(lo), "=r"(hi) : "l"(v));
    return __uint_as_float(lo) + __uint_as_float(hi);
}

__device__ float        g_sums[KC * DIM];    // incremental membership sums
__device__ float        g_cnts[KC];          // incremental counts
__device__ int          g_idx[NP];
__device__ unsigned int g_dirty[2][16];      // parity bitmaps of changed clusters
__device__ int          g_ndirty[2];         // distinct dirty-cluster counts
__device__ unsigned int g_bar_cnt;
__device__ volatile unsigned int g_bar_gen;

// Sense-reversing grid barrier; grid == #SMs, 1 block/SM (smem-forced).
__device__ __forceinline__ void grid_sync() {
    __syncthreads();
    if (threadIdx.x == 0) {
        __threadfence();
        unsigned int gen = g_bar_gen;
        if (atomicAdd(&g_bar_cnt, 1u) == gridDim.x - 1u) {
            g_bar_cnt = 0u;
            __threadfence();
            g_bar_gen = gen + 1u;
        } else {
            while (g_bar_gen == gen) { __nanosleep(32); }
        }
        __threadfence();
    }
    __syncthreads();
}

// One GEMM+argmin pass over PPN point-groups starting at slotbase.
template<int PPN>
__device__ __forceinline__ void gemm_pass(
    const ulonglong2* __restrict__ cT,      // stride KCS
    const ulonglong2* __restrict__ pT,      // stride PSLOT
    const float* __restrict__ s_csq,
    int* __restrict__ s_best,
    const int tx, const int ty, const int slotbase)
{
    float bv[PPN];
    int   bi[PPN];
    #pragma unroll
    for (int pp = 0; pp < PPN; ++pp) { bv[pp] = BIGF; bi[pp] = 0; }

    const int pbase = slotbase + ty;
    #pragma unroll 1
    for (int kb = 0; kb < 4; ++kb) {
        const int cbase = kb * 128 + tx;
        ull acc[PPN][8];
        #pragma unroll
        for (int pp = 0; pp < PPN; ++pp)
            #pragma unroll
            for (int cc = 0; cc < 8; ++cc) acc[pp][cc] = 0ull;

        #pragma unroll 1
        for (int j = 0; j < 16; ++j) {
            ulonglong2 cf[8];
            #pragma unroll
            for (int cc = 0; cc < 8; ++cc)
                cf[cc] = cT[j * KCS + cbase + cc * 16];
            ulonglong2 pf[PPN];
            #pragma unroll
            for (int pp = 0; pp < PPN; ++pp)
                pf[pp] = pT[j * PSLOT + pbase + pp * 16];
            #pragma unroll
            for (int pp = 0; pp < PPN; ++pp) {
                #pragma unroll
                for (int cc = 0; cc < 8; ++cc) {
                    FMA2(acc[pp][cc], pf[pp].x, cf[cc].x, acc[pp][cc]);
                    FMA2(acc[pp][cc], pf[pp].y, cf[cc].y, acc[pp][cc]);
                }
            }
        }
        #pragma unroll
        for (int cc = 0; cc < 8; ++cc) {
            const int ci = cbase + cc * 16;
            const float cq = s_csq[ci];
            #pragma unroll
            for (int pp = 0; pp < PPN; ++pp) {
                float d = fmaf(-2.f, f32x2_hsum(acc[pp][cc]), cq);
                // ci strictly ascends per thread -> strict < == first-min
                if (d < bv[pp]) { bv[pp] = d; bi[pp] = ci; }
            }
        }
    }
    // reduce across the 16 tx lanes (two independent halves per warp)
    #pragma unroll
    for (int pp = 0; pp < PPN; ++pp) {
        float v = bv[pp];
        int   i2 = bi[pp];
        #pragma unroll
        for (int off = 1; off < 16; off <<= 1) {
            float ov = __shfl_xor_sync(0xFFFFFFFFu, v, off);
            int   oi = __shfl_xor_sync(0xFFFFFFFFu, i2, off);
            if (ov < v || (ov == v && oi < i2)) { v = ov; i2 = oi; }
        }
        if (tx == 0) s_best[slotbase + pp * 16 + ty] = i2;
    }
}

__global__ void __launch_bounds__(TPB, 1)
kmeans_persistent_kernel(const float* __restrict__ embeds,
                         const float* __restrict__ init_cent,
                         float* __restrict__ out)
{
    extern __shared__ float s_dyn[];
    float4* s_centT = (float4*)s_dyn;                  // 16*KCS float4 (128.2KB)
    float4* s_pts   = s_centT + 16 * KCS;              // 16*PSLOT float4 (64KB)
    float*  s_csq   = (float*)(s_pts + 16 * PSLOT);    // KCP
    float*  s_rden  = s_csq + KCP;                     // KCP
    int*    s_best  = (int*)(s_rden + KCP);            // PSLOT
    int*    s_dlist = s_best + PSLOT;                  // 160
    int*    s_dn    = s_dlist + 160;                   // 1

    const int tid  = threadIdx.x;
    const int b    = blockIdx.x;
    const int G    = gridDim.x;
    const int gtid = b * TPB + tid;
    const int nth  = G * TPB;
    const int ty   = tid >> 4;          // 0..15
    const int tx   = tid & 15;          // 0..15

    // ---------------- global init (fresh every launch) ----------------
    for (int i = gtid; i < KC * DIM; i += nth) g_sums[i] = 0.f;
    for (int k = gtid; k < KC; k += nth)       g_cnts[k] = 0.f;
    for (int i = gtid; i < NP; i += nth)       g_idx[i] = -1;
    if (gtid < 16) { g_dirty[0][gtid] = 0u; g_dirty[1][gtid] = 0u; }
    if (gtid == 16) { g_ndirty[0] = 0; g_ndirty[1] = 0; }

    // ---- this block's points -> SMEM transposed (slot i <-> p = b + G*i) ----
    const int npts = (NP - 1 - b) / G + 1;   // 197 or 198 (<= 208 tiled)
    {
        const int i = tid;                    // PSLOT == TPB
        const int p = b + G * i;
        const bool v = (i < npts);
        const float4* ep = (const float4*)embeds + (size_t)p * 16;
        #pragma unroll
        for (int j = 0; j < 16; ++j)
            s_pts[j * PSLOT + i] = v ? ep[j] : make_float4(0.f, 0.f, 0.f, 0.f);
    }

    // ---- initial centroids -> SMEM (transposed) ----
    for (int i = tid; i < 16 * KCP; i += TPB) {
        int c = i >> 4, j = i & 15;
        float4 v = (c < KC) ? *(const float4*)(init_cent + c * DIM + 4 * j)
                            : make_float4(0.f, 0.f, 0.f, 0.f);
        s_centT[j * KCS + c] = v;
    }
    __syncthreads();
    for (int c = tid; c < KCP; c += TPB) {
        if (c < KC) {
            float a = 0.f;
            #pragma unroll
            for (int j = 0; j < 16; ++j) {
                float4 v = s_centT[j * KCS + c];
                a = fmaf(v.x, v.x, fmaf(v.y, v.y, fmaf(v.z, v.z, fmaf(v.w, v.w, a))));
            }
            s_csq[c] = a;
        } else {
            s_csq[c] = BIGF;
        }
    }

    grid_sync();

    for (int iter = 0; iter < MAX_ITERS; ++iter) {
        // ---- distance GEMM + fused argmin over 208 slots ----
        const ulonglong2* cT = (const ulonglong2*)s_centT;
        const ulonglong2* pT = (const ulonglong2*)s_pts;
        gemm_pass<8>(cT, pT, s_csq, s_best, tx, ty, 0);    // slots   0..127
        gemm_pass<5>(cT, pT, s_csq, s_best, tx, ty, 128);  // slots 128..207
        __syncthreads();

        // ---- epilogue: incremental sums + dirty marking (only on change) ----
        {
            const int par = iter & 1;
            const int p = b + G * tid;
            bool ch = false;
            int best = 0, old = -2;
            if (tid < npts) {
                best = s_best[tid];
                old = g_idx[p];
                ch = (old != best);
            }
            if (ch) {
                if (old >= 0) {
                    float* sp = g_sums + old * DIM;
                    #pragma unroll
                    for (int j = 0; j < 16; ++j) {
                        float4 v = s_pts[j * PSLOT + tid];
                        atomicAdd((float4*)(sp + 4 * j),
                                  make_float4(-v.x, -v.y, -v.z, -v.w));
                    }
                    atomicAdd(&g_cnts[old], -1.0f);
                    unsigned m = 1u << (old & 31);
                    unsigned prev = atomicOr(&g_dirty[par][old >> 5], m);
                    if (!(prev & m)) atomicAdd(&g_ndirty[par], 1);
                }
                float* sp = g_sums + best * DIM;
                #pragma unroll
                for (int j = 0; j < 16; ++j)
                    atomicAdd((float4*)(sp + 4 * j), s_pts[j * PSLOT + tid]);
                atomicAdd(&g_cnts[best], 1.0f);
                unsigned m = 1u << (best & 31);
                unsigned prev = atomicOr(&g_dirty[par][best >> 5], m);
                if (!(prev & m)) atomicAdd(&g_ndirty[par], 1);
                g_idx[p] = best;
            }
        }

        grid_sync();

        const int par = iter & 1;
        const int cnt = *(volatile int*)&g_ndirty[par];

        // reset other parity for iter+2 (next epilogue of that parity is a
        // full GEMM away on every block - ordered in practice)
        if (gtid < 16) g_dirty[par ^ 1][gtid] = 0u;
        if (gtid == 16) g_ndirty[par ^ 1] = 0;

        if (cnt == 0) break;                 // assignment fixed point

        // ---- staging: fold centroid update into SMEM refresh ----
        if (cnt >= FULLTH) {
            // full restage (coalesced reads of g_sums, conflict-free STS)
            for (int c = tid; c < KC; c += TPB)
                s_rden[c] = 1.0f / (g_cnts[c] + EPSV);
            __syncthreads();
            for (int i = tid; i < 16 * KCP; i += TPB) {
                int c = i >> 4, j = i & 15;
                if (c < KC) {
                    float4 s = *(const float4*)(g_sums + c * DIM + 4 * j);
                    float r = s_rden[c];
                    s_centT[j * KCS + c] =
                        make_float4(s.x * r, s.y * r, s.z * r, s.w * r);
                }
            }
            __syncthreads();
            for (int c = tid; c < KC; c += TPB) {
                float a = 0.f;
                #pragma unroll
                for (int j = 0; j < 16; ++j) {
                    float4 v = s_centT[j * KCS + c];
                    a = fmaf(v.x, v.x, fmaf(v.y, v.y, fmaf(v.z, v.z, fmaf(v.w, v.w, a))));
                }
                s_csq[c] = a;
            }
        } else {
            // sparse restage: only dirty clusters, 16 lanes per cluster
            if (tid == 0) *s_dn = 0;
            __syncthreads();
            if (tid < 16) {
                unsigned w = g_dirty[par][tid];
                while (w) {
                    int bit = __ffs(w) - 1;
                    w &= w - 1u;
                    int pos = atomicAdd(s_dn, 1);
                    s_dlist[pos] = tid * 32 + bit;
                }
            }
            __syncthreads();
            const int dn = *s_dn;
            const int grp = tid >> 4, lane = tid & 15;
            const int nrounds = (dn + 15) >> 4;
            for (int r = 0; r < nrounds; ++r) {
                const int d = r * 16 + grp;
                const bool act = (d < dn);
                int c = act ? s_dlist[d] : 0;
                float4 v = make_float4(0.f, 0.f, 0.f, 0.f);
                if (act) {
                    float4 s = *(const float4*)(g_sums + c * DIM + 4 * lane);
                    float rd = 1.0f / (g_cnts[c] + EPSV);   // same op as full mode
                    v = make_float4(s.x * rd, s.y * rd, s.z * rd, s.w * rd);
                    s_centT[lane * KCS + c] = v;
                }
                float cs = fmaf(v.x, v.x, fmaf(v.y, v.y, fmaf(v.z, v.z, v.w * v.w)));
                #pragma unroll
                for (int off = 1; off < 16; off <<= 1)
                    cs += __shfl_xor_sync(0xFFFFFFFFu, cs, off, 16);
                if (act && lane == 0) s_csq[c] = cs;
            }
        }
        __syncthreads();
    }

    // ---- outputs: centroids [KC*DIM] (exact div), idxs [NP], counts [KC] ----
    for (int i = gtid; i < KC * DIM; i += nth) {
        int k = i >> 6;
        out[i] = g_sums[i] / (g_cnts[k] + EPSV);
    }
    for (int i = gtid; i < NP; i += nth)
        out[KC * DIM + i] = (float)g_idx[i];
    for (int i = gtid; i < KC; i += nth)
        out[KC * DIM + NP + i] = g_cnts[i];
}

extern "C" void kernel_launch(void* const* d_in, const int* in_sizes, int n_in,
                              void* d_out, int out_size)
{
    const float* embeds = (const float*)d_in[0];
    const float* initc  = (const float*)d_in[1];
    if (n_in >= 2 && in_sizes[0] == KC * DIM && in_sizes[1] == NP * DIM) {
        embeds = (const float*)d_in[1];
        initc  = (const float*)d_in[0];
    }
    float* out = (float*)d_out;

    int dev = 0;
    cudaGetDevice(&dev);
    int nsm = 0;
    cudaDeviceGetAttribute(&nsm, cudaDevAttrMultiProcessorCount, dev);

    size_t smem = (size_t)(16 * KCS + 16 * PSLOT) * sizeof(float4)
                + (size_t)2 * KCP * sizeof(float)          // csq + rden
                + (size_t)(PSLOT + 160 + 1) * sizeof(int); // best + dlist + dn
    cudaFuncSetAttribute(kmeans_persistent_kernel,
                         cudaFuncAttributeMaxDynamicSharedMemorySize, (int)smem);

    kmeans_persistent_kernel<<<nsm, TPB, smem>>>(embeds, initc, out);
}